// round 1
// baseline (speedup 1.0000x reference)
#include <cuda_runtime.h>
#include <math.h>

#define NN   50000
#define NE   800000
#define NEL  850000
#define NG   64
#define FP   112      // feats row pitch (110 used + 2 zero pad)
#define NF   110
#define MD   32
#define EH   128
#define NH   128
#define NIN  142
#define EFD  222

// -------- device scratch (no allocations allowed) --------
__device__ float g_feats[NN * FP];     // node features, padded
__device__ float g_P[(size_t)NN * 256];// [n][0:128]=feats@W1_dst, [n][128:256]=feats@W1_src
__device__ float g_mi[NN * MD];        // aggregated messages
__device__ float g_ea[NE * 2];         // (edge_attr, rel_dist) per real edge
__device__ float g_mean[NG];
__device__ float g_rstd[NG];

__device__ __forceinline__ float silu_f(float x) {
    return x * (1.0f / (1.0f + __expf(-x)));
}

__device__ __forceinline__ int lb_i(const int* __restrict__ a, int n, int v) {
    int lo = 0, hi = n;
    while (lo < hi) { int m = (lo + hi) >> 1; if (a[m] < v) lo = m + 1; else hi = m; }
    return lo;
}

// -------------------- embed --------------------
__global__ void embed_kernel(const float* __restrict__ x,
    const float* __restrict__ e0, const float* __restrict__ e1,
    const float* __restrict__ e2, const float* __restrict__ e3,
    const float* __restrict__ e4, const float* __restrict__ e5,
    const float* __restrict__ e6, const float* __restrict__ e7,
    const float* __restrict__ e8, const float* __restrict__ e9)
{
    long idx = (long)blockIdx.x * blockDim.x + threadIdx.x;
    if (idx >= (long)NN * FP) return;
    int n = (int)(idx / FP), k = (int)(idx % FP);
    float v = 0.f;
    if (k < 6) {
        int keep = (k == 0) ? 0 : (10 + k);      // {0,11,12,13,14,15}
        v = x[n * 16 + keep];
    } else if (k < 38) {
        int code = (int)x[n * 16 + 1];
        v = e0[code * 32 + (k - 6)];
    } else if (k < 110) {
        int t = (k - 38) >> 3, c = (k - 38) & 7;
        int code = (int)x[n * 16 + 2 + t];
        const float* es[9] = {e1, e2, e3, e4, e5, e6, e7, e8, e9};
        v = es[t][code * 8 + c];
    }
    g_feats[idx] = v;
}

// -------------------- edge attr + rel dist (layer-invariant) --------------------
__global__ void ea_kernel(const int* __restrict__ ei,
                          const float* __restrict__ eattr,
                          const float* __restrict__ pos)
{
    int e = blockIdx.x * blockDim.x + threadIdx.x;
    if (e >= NE) return;
    int s = ei[e], d = ei[NE + e];
    float dx = pos[s * 3 + 0] - pos[d * 3 + 0];
    float dy = pos[s * 3 + 1] - pos[d * 3 + 1];
    float dz = pos[s * 3 + 2] - pos[d * 3 + 2];
    g_ea[2 * e + 0] = eattr[e];
    g_ea[2 * e + 1] = dx * dx + dy * dy + dz * dz;
}

// -------------------- P = feats @ [W1_dst | W1_src]  (per half) --------------------
__global__ void precompP_kernel(const float* __restrict__ w1, int l)
{
    __shared__ float Xs[64 * 112];
    __shared__ float Ws[8 * 128];
    int m0 = blockIdx.x * 64;
    int half = blockIdx.y;              // 0: rows 0..109 (dst), 1: rows 110..219 (src)
    int row0 = half * 110;
    int tid = threadIdx.x;

    for (int i = tid; i < 64 * 112; i += 256) {
        int n = m0 + (i / 112);
        Xs[i] = (n < NN) ? g_feats[(size_t)n * FP + (i % 112)] : 0.f;
    }
    int tx = tid & 15, ty = tid >> 4;
    float acc[4][8];
    #pragma unroll
    for (int i = 0; i < 4; i++)
        #pragma unroll
        for (int j = 0; j < 8; j++) acc[i][j] = 0.f;

    const float* wbase = w1 + (size_t)l * EFD * EH;
    for (int kt = 0; kt < 14; ++kt) {
        __syncthreads();
        for (int i = tid; i < 1024; i += 256) {
            int r = i >> 7, c = i & 127, k = kt * 8 + r;
            Ws[i] = (k < 110) ? wbase[(size_t)(row0 + k) * EH + c] : 0.f;
        }
        __syncthreads();
        #pragma unroll
        for (int kk = 0; kk < 8; kk++) {
            float a[4];
            #pragma unroll
            for (int i = 0; i < 4; i++)
                a[i] = Xs[(ty * 4 + i) * 112 + kt * 8 + kk];
            float4 b0 = *(const float4*)&Ws[kk * 128 + tx * 8];
            float4 b1 = *(const float4*)&Ws[kk * 128 + tx * 8 + 4];
            #pragma unroll
            for (int i = 0; i < 4; i++) {
                acc[i][0] += a[i] * b0.x; acc[i][1] += a[i] * b0.y;
                acc[i][2] += a[i] * b0.z; acc[i][3] += a[i] * b0.w;
                acc[i][4] += a[i] * b1.x; acc[i][5] += a[i] * b1.y;
                acc[i][6] += a[i] * b1.z; acc[i][7] += a[i] * b1.w;
            }
        }
    }
    #pragma unroll
    for (int i = 0; i < 4; i++) {
        int n = m0 + ty * 4 + i;
        if (n < NN) {
            float4* p = (float4*)&g_P[(size_t)n * 256 + half * 128 + tx * 8];
            p[0] = make_float4(acc[i][0], acc[i][1], acc[i][2], acc[i][3]);
            p[1] = make_float4(acc[i][4], acc[i][5], acc[i][6], acc[i][7]);
        }
    }
}

// -------------------- zero m_i --------------------
__global__ void zero_mi_kernel()
{
    int i = blockIdx.x * blockDim.x + threadIdx.x;
    if (i < NN * MD) g_mi[i] = 0.f;
}

// -------------------- fused edge MLP + scatter --------------------
// smem floats: Hs 64*130 | W2s 4096 | w220 128 | w221 128 | b1s 128 | b2s 32 | ea0s 64 | dds 64 | srcs 64i | dsts 64i
#define EDGE_SMEM ((64*130 + 4096 + 128*3 + 32 + 64 + 64) * 4 + 64 * 2 * 4)

__global__ void edge_kernel(const int* __restrict__ ei,
    const float* __restrict__ w1, const float* __restrict__ b1,
    const float* __restrict__ w2, const float* __restrict__ b2, int l)
{
    extern __shared__ float sm[];
    float* Hs   = sm;
    float* W2s  = Hs + 64 * 130;
    float* w220 = W2s + 4096;
    float* w221 = w220 + 128;
    float* b1s  = w221 + 128;
    float* b2s  = b1s + 128;
    float* ea0s = b2s + 32;
    float* dds  = ea0s + 64;
    int*   srcs = (int*)(dds + 64);
    int*   dsts = srcs + 64;

    int tid = threadIdx.x;
    int e0 = blockIdx.x * 64;
    const float* w1b = w1 + (size_t)l * EFD * EH;

    if (tid < 128) {
        w220[tid] = w1b[220 * EH + tid];
        w221[tid] = w1b[221 * EH + tid];
        b1s[tid]  = b1[l * EH + tid];
    }
    if (tid >= 128 && tid < 160) b2s[tid - 128] = b2[l * MD + (tid - 128)];
    for (int i = tid; i < 4096; i += 256)
        W2s[i] = w2[(size_t)l * EH * MD + i];
    for (int i = tid; i < 64; i += 256) {
        int e = e0 + i;
        int s = -1, d = -1; float a = 0.f, dd = 0.f;
        if (e < NEL) {
            if (e < NE) { s = ei[e]; d = ei[NE + e]; a = g_ea[2 * e]; dd = g_ea[2 * e + 1]; }
            else        { s = d = e - NE; }
        }
        srcs[i] = s; dsts[i] = d; ea0s[i] = a; dds[i] = dd;
    }
    __syncthreads();

    // phase 1: hidden = silu(Pd[dst] + Ps[src] + ea*w220 + dist*w221 + b1)
    #pragma unroll 4
    for (int it = 0; it < 32; ++it) {
        int idx = it * 256 + tid;
        int e = idx >> 7, k = idx & 127;
        int d = dsts[e];
        float v = 0.f;
        if (d >= 0) {
            int s = srcs[e];
            v = g_P[(size_t)d * 256 + k] + g_P[(size_t)s * 256 + 128 + k]
              + ea0s[e] * w220[k] + dds[e] * w221[k] + b1s[k];
            v = silu_f(v);
        }
        Hs[e * 130 + k] = v;
    }
    __syncthreads();

    // phase 2: m = silu(H @ W2 + b2), scatter-add to g_mi[dst]
    int tx = tid & 3, ty = tid >> 2;   // ty = local edge 0..63, tx*8 = col group
    int j0 = tx * 8;
    float acc[8];
    #pragma unroll
    for (int j = 0; j < 8; j++) acc[j] = 0.f;

    #pragma unroll 8
    for (int k = 0; k < 128; k++) {
        float a = Hs[ty * 130 + k];
        float4 bA = *(const float4*)&W2s[k * 32 + j0];
        float4 bB = *(const float4*)&W2s[k * 32 + j0 + 4];
        acc[0] += a * bA.x; acc[1] += a * bA.y; acc[2] += a * bA.z; acc[3] += a * bA.w;
        acc[4] += a * bB.x; acc[5] += a * bB.y; acc[6] += a * bB.z; acc[7] += a * bB.w;
    }
    int d = dsts[ty];
    if (d >= 0) {
        #pragma unroll
        for (int j = 0; j < 8; j++) {
            float m = silu_f(acc[j] + b2s[j0 + j]);
            atomicAdd(&g_mi[(size_t)d * MD + j0 + j], m);
        }
    }
}

// -------------------- per-graph LN stats (mean, rstd) --------------------
__global__ void stats_kernel(const int* __restrict__ batch)
{
    int g = blockIdx.x;
    __shared__ int s_lo, s_hi;
    __shared__ float red[256], red2[256];
    int tid = threadIdx.x;
    if (tid == 0) { s_lo = lb_i(batch, NN, g); s_hi = lb_i(batch, NN, g + 1); }
    __syncthreads();
    int lo = s_lo, hi = s_hi;
    long total = (long)(hi - lo) * NF;
    float s = 0.f, s2 = 0.f;
    for (long p = tid; p < total; p += 256) {
        int n = lo + (int)(p / NF), k = (int)(p % NF);
        float v = g_feats[(size_t)n * FP + k];
        s += v; s2 += v * v;
    }
    red[tid] = s; red2[tid] = s2;
    __syncthreads();
    for (int st = 128; st > 0; st >>= 1) {
        if (tid < st) { red[tid] += red[tid + st]; red2[tid] += red2[tid + st]; }
        __syncthreads();
    }
    if (tid == 0) {
        float cnt = (float)((hi - lo) > 1 ? (hi - lo) : 1);
        float denom = cnt * 110.f;
        float mean = red[0] / denom;
        float var = red2[0] / denom - mean * mean;
        var = fmaxf(var, 0.f);
        g_mean[g] = mean;
        g_rstd[g] = rsqrtf(var + 1e-5f);
    }
}

// -------------------- fused node MLP: LN -> GEMM1+silu -> GEMM2 -> residual --------------------
#define NODE_SMEM ((64*144 + 64*132 + 1024) * 4)

__global__ void node_kernel(const int* __restrict__ batch,
    const float* __restrict__ nw1, const float* __restrict__ nb1,
    const float* __restrict__ nw2, const float* __restrict__ nb2,
    const float* __restrict__ lnw, const float* __restrict__ lnb, int l)
{
    extern __shared__ float sm[];
    float* Xs = sm;             // 64 x 144 (0..109 ln(feats), 110..141 m_i, rest 0)
    float* Hs = Xs + 64 * 144;  // 64 x 132
    float* Ws = Hs + 64 * 132;  // 1024 (reused by both GEMMs)

    int tid = threadIdx.x;
    int m0 = blockIdx.x * 64;

    for (int i = tid; i < 64 * 144; i += 256) {
        int n = m0 + i / 144, k = i % 144;
        float v = 0.f;
        if (n < NN) {
            if (k < 110) {
                int g = batch[n];
                float f = g_feats[(size_t)n * FP + k];
                v = lnw[l * NF + k] * ((f - g_mean[g]) * g_rstd[g]) + lnb[l * NF + k];
            } else if (k < 142) {
                v = g_mi[(size_t)n * MD + (k - 110)];
            }
        }
        Xs[i] = v;
    }

    int tx = tid & 15, ty = tid >> 4;
    float acc[4][8];
    #pragma unroll
    for (int i = 0; i < 4; i++)
        #pragma unroll
        for (int j = 0; j < 8; j++) acc[i][j] = 0.f;

    const float* w1b = nw1 + (size_t)l * NIN * NH;
    for (int kt = 0; kt < 18; ++kt) {
        __syncthreads();
        for (int i = tid; i < 1024; i += 256) {
            int r = i >> 7, c = i & 127, k = kt * 8 + r;
            Ws[i] = (k < NIN) ? w1b[(size_t)k * NH + c] : 0.f;
        }
        __syncthreads();
        #pragma unroll
        for (int kk = 0; kk < 8; kk++) {
            float a[4];
            #pragma unroll
            for (int i = 0; i < 4; i++)
                a[i] = Xs[(ty * 4 + i) * 144 + kt * 8 + kk];
            float4 b0 = *(const float4*)&Ws[kk * 128 + tx * 8];
            float4 b1 = *(const float4*)&Ws[kk * 128 + tx * 8 + 4];
            #pragma unroll
            for (int i = 0; i < 4; i++) {
                acc[i][0] += a[i] * b0.x; acc[i][1] += a[i] * b0.y;
                acc[i][2] += a[i] * b0.z; acc[i][3] += a[i] * b0.w;
                acc[i][4] += a[i] * b1.x; acc[i][5] += a[i] * b1.y;
                acc[i][6] += a[i] * b1.z; acc[i][7] += a[i] * b1.w;
            }
        }
    }
    // silu + bias -> Hs
    #pragma unroll
    for (int i = 0; i < 4; i++)
        #pragma unroll
        for (int j = 0; j < 8; j++) {
            float v = silu_f(acc[i][j] + nb1[l * NH + tx * 8 + j]);
            Hs[(ty * 4 + i) * 132 + tx * 8 + j] = v;
        }

    // GEMM2: [64 x 128] @ [128 x 110] (7 cols per thread over 112 padded)
    float a2[4][7];
    #pragma unroll
    for (int i = 0; i < 4; i++)
        #pragma unroll
        for (int j = 0; j < 7; j++) a2[i][j] = 0.f;

    const float* w2b = nw2 + (size_t)l * NH * NF;
    for (int kt = 0; kt < 16; ++kt) {
        __syncthreads();
        for (int i = tid; i < 8 * 112; i += 256) {
            int r = i / 112, c = i % 112, k = kt * 8 + r;
            Ws[i] = (c < NF) ? w2b[(size_t)k * NF + c] : 0.f;
        }
        __syncthreads();
        #pragma unroll
        for (int kk = 0; kk < 8; kk++) {
            float a[4];
            #pragma unroll
            for (int i = 0; i < 4; i++)
                a[i] = Hs[(ty * 4 + i) * 132 + kt * 8 + kk];
            #pragma unroll
            for (int j = 0; j < 7; j++) {
                float b = Ws[kk * 112 + tx * 7 + j];
                #pragma unroll
                for (int i = 0; i < 4; i++) a2[i][j] += a[i] * b;
            }
        }
    }

    #pragma unroll
    for (int i = 0; i < 4; i++) {
        int n = m0 + ty * 4 + i;
        if (n < NN) {
            #pragma unroll
            for (int j = 0; j < 7; j++) {
                int c = tx * 7 + j;
                if (c < NF)
                    g_feats[(size_t)n * FP + c] += a2[i][j] + nb2[l * NF + c];
            }
        }
    }
}

// -------------------- global mean pool --------------------
__global__ void pool_kernel(const int* __restrict__ batch, float* __restrict__ out)
{
    int g = blockIdx.x;
    __shared__ int s_lo, s_hi;
    if (threadIdx.x == 0) { s_lo = lb_i(batch, NN, g); s_hi = lb_i(batch, NN, g + 1); }
    __syncthreads();
    int k = threadIdx.x;
    if (k >= NF) return;
    int lo = s_lo, hi = s_hi;
    float s = 0.f;
    for (int n = lo; n < hi; n++) s += g_feats[(size_t)n * FP + k];
    int cnt = (hi - lo) > 1 ? (hi - lo) : 1;
    out[g * NF + k] = s / (float)cnt;
}

// -------------------- launch --------------------
extern "C" void kernel_launch(void* const* d_in, const int* in_sizes, int n_in,
                              void* d_out, int out_size)
{
    const float* x     = (const float*)d_in[0];
    const int*   ei    = (const int*)  d_in[1];
    const float* eattr = (const float*)d_in[2];
    const float* pos   = (const float*)d_in[3];
    const int*   batch = (const int*)  d_in[4];
    const float* emb[10];
    for (int i = 0; i < 10; i++) emb[i] = (const float*)d_in[5 + i];
    const float* ew1 = (const float*)d_in[15];
    const float* eb1 = (const float*)d_in[16];
    const float* ew2 = (const float*)d_in[17];
    const float* eb2 = (const float*)d_in[18];
    const float* nw1 = (const float*)d_in[19];
    const float* nb1 = (const float*)d_in[20];
    const float* nw2 = (const float*)d_in[21];
    const float* nb2 = (const float*)d_in[22];
    const float* lnw = (const float*)d_in[23];
    const float* lnb = (const float*)d_in[24];
    float* out = (float*)d_out;

    cudaFuncSetAttribute(edge_kernel, cudaFuncAttributeMaxDynamicSharedMemorySize, EDGE_SMEM);
    cudaFuncSetAttribute(node_kernel, cudaFuncAttributeMaxDynamicSharedMemorySize, NODE_SMEM);

    embed_kernel<<<(NN * FP + 255) / 256, 256>>>(x, emb[0], emb[1], emb[2], emb[3],
                                                 emb[4], emb[5], emb[6], emb[7], emb[8], emb[9]);
    ea_kernel<<<(NE + 255) / 256, 256>>>(ei, eattr, pos);

    for (int l = 0; l < 2; l++) {
        precompP_kernel<<<dim3((NN + 63) / 64, 2), 256>>>(ew1, l);
        zero_mi_kernel<<<(NN * MD + 255) / 256, 256>>>();
        edge_kernel<<<(NEL + 63) / 64, 256, EDGE_SMEM>>>(ei, ew1, eb1, ew2, eb2, l);
        stats_kernel<<<NG, 256>>>(batch);
        node_kernel<<<(NN + 63) / 64, 256, NODE_SMEM>>>(batch, nw1, nb1, nw2, nb2, lnw, lnb, l);
    }
    pool_kernel<<<NG, 128>>>(batch, out);
}

// round 2
// speedup vs baseline: 1.2987x; 1.2987x over previous
#include <cuda_runtime.h>
#include <math.h>

#define NN   50000
#define NE   800000
#define NEL  850000
#define NG   64
#define FP   112      // feats row pitch (110 used + 2 zero pad)
#define NF   110
#define MD   32
#define EH   128
#define NH   128
#define NIN  142
#define EFD  222

// -------- device scratch (no allocations allowed) --------
__device__ float g_feats[NN * FP];
__device__ float g_P[(size_t)NN * 256];   // [n][0:128]=feats@W1_dst, [n][128:256]=feats@W1_src
__device__ float g_mi[NN * MD];
__device__ float g_ea[NE * 2];
__device__ float g_hid[(size_t)NN * NH];
__device__ float g_sum[NG], g_sum2[NG];
__device__ float g_mean[NG], g_rstd[NG];

__device__ __forceinline__ float silu_f(float x) {
    return x * (1.0f / (1.0f + __expf(-x)));
}

__device__ __forceinline__ int lb_i(const int* __restrict__ a, int n, int v) {
    int lo = 0, hi = n;
    while (lo < hi) { int m = (lo + hi) >> 1; if (a[m] < v) lo = m + 1; else hi = m; }
    return lo;
}

// -------------------- embed (+ zero g_mi) --------------------
__global__ void embed_kernel(const float* __restrict__ x,
    const float* __restrict__ e0, const float* __restrict__ e1,
    const float* __restrict__ e2, const float* __restrict__ e3,
    const float* __restrict__ e4, const float* __restrict__ e5,
    const float* __restrict__ e6, const float* __restrict__ e7,
    const float* __restrict__ e8, const float* __restrict__ e9)
{
    long idx = (long)blockIdx.x * blockDim.x + threadIdx.x;
    if (idx < (long)NN * MD) g_mi[idx] = 0.f;
    if (idx >= (long)NN * FP) return;
    int n = (int)(idx / FP), k = (int)(idx % FP);
    float v = 0.f;
    if (k < 6) {
        int keep = (k == 0) ? 0 : (10 + k);
        v = x[n * 16 + keep];
    } else if (k < 38) {
        int code = (int)x[n * 16 + 1];
        v = e0[code * 32 + (k - 6)];
    } else if (k < 110) {
        int t = (k - 38) >> 3, c = (k - 38) & 7;
        int code = (int)x[n * 16 + 2 + t];
        const float* es[9] = {e1, e2, e3, e4, e5, e6, e7, e8, e9};
        v = es[t][code * 8 + c];
    }
    g_feats[idx] = v;
}

// -------------------- edge attr + rel dist --------------------
__global__ void ea_kernel(const int* __restrict__ ei,
                          const float* __restrict__ eattr,
                          const float* __restrict__ pos)
{
    int e = blockIdx.x * blockDim.x + threadIdx.x;
    if (e >= NE) return;
    int s = ei[e], d = ei[NE + e];
    float dx = pos[s * 3 + 0] - pos[d * 3 + 0];
    float dy = pos[s * 3 + 1] - pos[d * 3 + 1];
    float dz = pos[s * 3 + 2] - pos[d * 3 + 2];
    g_ea[2 * e + 0] = eattr[e];
    g_ea[2 * e + 1] = dx * dx + dy * dy + dz * dz;
}

// -------------------- P = feats @ [W1_dst | W1_src] (resident W, barrier-free k-loop) ----
#define PP_SMEM ((64*112 + 112*128) * 4)
__global__ void precompP_kernel(const float* __restrict__ w1, int l)
{
    extern __shared__ float sm[];
    float* Xs = sm;             // 64 x 112
    float* Ws = sm + 64 * 112;  // 112 x 128 (rows 110,111 zero)
    int tid = threadIdx.x;
    int m0 = blockIdx.x * 64;
    int half = blockIdx.y;

    if (blockIdx.x == 0 && half == 0 && tid < 2 * NG) {
        if (tid < NG) g_sum[tid] = 0.f; else g_sum2[tid - NG] = 0.f;
    }

    const float* wbase = w1 + (size_t)l * EFD * EH + (size_t)half * 110 * EH;
    for (int i = tid; i < 112 * 32; i += 256) {
        int r = i >> 5, c = (i & 31) * 4;
        float4 w = make_float4(0.f, 0.f, 0.f, 0.f);
        if (r < 110) w = *(const float4*)&wbase[(size_t)r * EH + c];
        *(float4*)&Ws[r * 128 + c] = w;
    }
    for (int i = tid; i < 64 * 28; i += 256) {
        int r = i / 28, c = (i % 28) * 4;
        int n = m0 + r;
        float4 v = make_float4(0.f, 0.f, 0.f, 0.f);
        if (n < NN) v = *(const float4*)&g_feats[(size_t)n * FP + c];
        *(float4*)&Xs[r * 112 + c] = v;
    }
    __syncthreads();

    int tx = tid & 15, ty = tid >> 4;
    float acc[4][8];
    #pragma unroll
    for (int i = 0; i < 4; i++)
        #pragma unroll
        for (int j = 0; j < 8; j++) acc[i][j] = 0.f;

    for (int kt = 0; kt < 28; ++kt) {
        float av[4][4];
        #pragma unroll
        for (int i = 0; i < 4; i++) {
            float4 a = *(const float4*)&Xs[(ty * 4 + i) * 112 + kt * 4];
            av[i][0] = a.x; av[i][1] = a.y; av[i][2] = a.z; av[i][3] = a.w;
        }
        #pragma unroll
        for (int kk = 0; kk < 4; kk++) {
            float4 b0 = *(const float4*)&Ws[(kt * 4 + kk) * 128 + tx * 8];
            float4 b1 = *(const float4*)&Ws[(kt * 4 + kk) * 128 + tx * 8 + 4];
            #pragma unroll
            for (int i = 0; i < 4; i++) {
                float a = av[i][kk];
                acc[i][0] += a * b0.x; acc[i][1] += a * b0.y;
                acc[i][2] += a * b0.z; acc[i][3] += a * b0.w;
                acc[i][4] += a * b1.x; acc[i][5] += a * b1.y;
                acc[i][6] += a * b1.z; acc[i][7] += a * b1.w;
            }
        }
    }
    #pragma unroll
    for (int i = 0; i < 4; i++) {
        int n = m0 + ty * 4 + i;
        if (n < NN) {
            float4* p = (float4*)&g_P[(size_t)n * 256 + half * 128 + tx * 8];
            p[0] = make_float4(acc[i][0], acc[i][1], acc[i][2], acc[i][3]);
            p[1] = make_float4(acc[i][4], acc[i][5], acc[i][6], acc[i][7]);
        }
    }
}

// -------------------- fused edge MLP + vector-RED scatter --------------------
// floats: Hs 128*132 | W2s 4096 | w220 128 | w221 128 | b1s 128 | b2s 32 | ea0s 128 | dds 128 ; ints: 256
#define EDGE_SMEM ((128*132 + 4096 + 128*3 + 32 + 128 + 128) * 4 + 256 * 4)
__global__ void edge_kernel(const int* __restrict__ ei,
    const float* __restrict__ w1, const float* __restrict__ b1,
    const float* __restrict__ w2, const float* __restrict__ b2, int l)
{
    extern __shared__ float sm[];
    float* Hs   = sm;               // 128 x 132
    float* W2s  = Hs + 128 * 132;   // 128 x 32
    float* w220 = W2s + 4096;
    float* w221 = w220 + 128;
    float* b1s  = w221 + 128;
    float* b2s  = b1s + 128;
    float* ea0s = b2s + 32;
    float* dds  = ea0s + 128;
    int*   srcs = (int*)(dds + 128);
    int*   dsts = srcs + 128;

    int tid = threadIdx.x;
    int e0 = blockIdx.x * 128;
    const float* w1b = w1 + (size_t)l * EFD * EH;

    if (tid < 128) {
        w220[tid] = w1b[220 * EH + tid];
        w221[tid] = w1b[221 * EH + tid];
        b1s[tid]  = b1[l * EH + tid];
        int e = e0 + tid;
        int s = -1, d = -1; float a = 0.f, dd = 0.f;
        if (e < NEL) {
            if (e < NE) { s = ei[e]; d = ei[NE + e]; a = g_ea[2 * e]; dd = g_ea[2 * e + 1]; }
            else        { s = d = e - NE; }
        }
        srcs[tid] = s; dsts[tid] = d; ea0s[tid] = a; dds[tid] = dd;
    } else if (tid < 160) {
        b2s[tid - 128] = b2[l * MD + (tid - 128)];
    }
    for (int i = tid; i < 1024; i += 256)
        *(float4*)&W2s[i * 4] = *(const float4*)&w2[(size_t)l * EH * MD + i * 4];
    __syncthreads();

    // phase 1: H = silu(Pd[dst] + Ps[src] + ea*w220 + dist*w221 + b1)  (one warp per edge)
    #pragma unroll
    for (int it = 0; it < 16; ++it) {
        int idx = it * 256 + tid;
        int e = idx >> 5;
        int k0 = (idx & 31) * 4;
        int d = dsts[e];
        float4 v = make_float4(0.f, 0.f, 0.f, 0.f);
        if (d >= 0) {
            int s = srcs[e];
            float4 pd = *(const float4*)&g_P[(size_t)d * 256 + k0];
            float4 ps = *(const float4*)&g_P[(size_t)s * 256 + 128 + k0];
            float a = ea0s[e], dd = dds[e];
            v.x = silu_f(pd.x + ps.x + a * w220[k0 + 0] + dd * w221[k0 + 0] + b1s[k0 + 0]);
            v.y = silu_f(pd.y + ps.y + a * w220[k0 + 1] + dd * w221[k0 + 1] + b1s[k0 + 1]);
            v.z = silu_f(pd.z + ps.z + a * w220[k0 + 2] + dd * w221[k0 + 2] + b1s[k0 + 2]);
            v.w = silu_f(pd.w + ps.w + a * w220[k0 + 3] + dd * w221[k0 + 3] + b1s[k0 + 3]);
        }
        *(float4*)&Hs[e * 132 + k0] = v;
    }
    __syncthreads();

    // phase 2: m = silu(H @ W2 + b2), vector-RED scatter to g_mi[dst]
    int tx = tid & 3, ty = tid >> 2;     // ty 0..63, edges {ty, ty+64}
    int j0 = tx * 8;
    float acc0[8], acc1[8];
    #pragma unroll
    for (int j = 0; j < 8; j++) { acc0[j] = 0.f; acc1[j] = 0.f; }

    for (int kt = 0; kt < 32; ++kt) {
        float4 A0 = *(const float4*)&Hs[ty * 132 + kt * 4];
        float4 A1 = *(const float4*)&Hs[(ty + 64) * 132 + kt * 4];
        float a0v[4] = {A0.x, A0.y, A0.z, A0.w};
        float a1v[4] = {A1.x, A1.y, A1.z, A1.w};
        #pragma unroll
        for (int kk = 0; kk < 4; kk++) {
            float4 bA = *(const float4*)&W2s[(kt * 4 + kk) * 32 + j0];
            float4 bB = *(const float4*)&W2s[(kt * 4 + kk) * 32 + j0 + 4];
            float a0 = a0v[kk], a1 = a1v[kk];
            acc0[0] += a0 * bA.x; acc0[1] += a0 * bA.y; acc0[2] += a0 * bA.z; acc0[3] += a0 * bA.w;
            acc0[4] += a0 * bB.x; acc0[5] += a0 * bB.y; acc0[6] += a0 * bB.z; acc0[7] += a0 * bB.w;
            acc1[0] += a1 * bA.x; acc1[1] += a1 * bA.y; acc1[2] += a1 * bA.z; acc1[3] += a1 * bA.w;
            acc1[4] += a1 * bB.x; acc1[5] += a1 * bB.y; acc1[6] += a1 * bB.z; acc1[7] += a1 * bB.w;
        }
    }
    int d0 = dsts[ty], d1 = dsts[ty + 64];
    if (d0 >= 0) {
        float4 r0 = make_float4(silu_f(acc0[0] + b2s[j0 + 0]), silu_f(acc0[1] + b2s[j0 + 1]),
                                silu_f(acc0[2] + b2s[j0 + 2]), silu_f(acc0[3] + b2s[j0 + 3]));
        float4 r1 = make_float4(silu_f(acc0[4] + b2s[j0 + 4]), silu_f(acc0[5] + b2s[j0 + 5]),
                                silu_f(acc0[6] + b2s[j0 + 6]), silu_f(acc0[7] + b2s[j0 + 7]));
        atomicAdd((float4*)&g_mi[(size_t)d0 * MD + j0], r0);
        atomicAdd((float4*)&g_mi[(size_t)d0 * MD + j0 + 4], r1);
    }
    if (d1 >= 0) {
        float4 r0 = make_float4(silu_f(acc1[0] + b2s[j0 + 0]), silu_f(acc1[1] + b2s[j0 + 1]),
                                silu_f(acc1[2] + b2s[j0 + 2]), silu_f(acc1[3] + b2s[j0 + 3]));
        float4 r1 = make_float4(silu_f(acc1[4] + b2s[j0 + 4]), silu_f(acc1[5] + b2s[j0 + 5]),
                                silu_f(acc1[6] + b2s[j0 + 6]), silu_f(acc1[7] + b2s[j0 + 7]));
        atomicAdd((float4*)&g_mi[(size_t)d1 * MD + j0], r0);
        atomicAdd((float4*)&g_mi[(size_t)d1 * MD + j0 + 4], r1);
    }
}

// -------------------- LN stats: partial (64x8 blocks) + final --------------------
__global__ void stats_partial_kernel(const int* __restrict__ batch)
{
    __shared__ int s_lo, s_hi;
    __shared__ float rs[8], rs2[8];
    int g = blockIdx.x, part = blockIdx.y;
    int tid = threadIdx.x;
    if (tid == 0) { s_lo = lb_i(batch, NN, g); s_hi = lb_i(batch, NN, g + 1); }
    __syncthreads();
    int total = (s_hi - s_lo) * FP;     // pad cols are zero -> harmless
    int chunk = (total + 7) >> 3;
    int st = part * chunk;
    int en = st + chunk; if (en > total) en = total;
    const float* base = g_feats + (size_t)s_lo * FP;
    float s = 0.f, s2 = 0.f;
    for (int i = st + tid; i < en; i += 256) { float v = base[i]; s += v; s2 += v * v; }
    #pragma unroll
    for (int o = 16; o; o >>= 1) {
        s  += __shfl_down_sync(0xffffffffu, s, o);
        s2 += __shfl_down_sync(0xffffffffu, s2, o);
    }
    if ((tid & 31) == 0) { rs[tid >> 5] = s; rs2[tid >> 5] = s2; }
    __syncthreads();
    if (tid == 0) {
        float a = 0.f, b = 0.f;
        for (int i = 0; i < 8; i++) { a += rs[i]; b += rs2[i]; }
        atomicAdd(&g_sum[g], a); atomicAdd(&g_sum2[g], b);
    }
}

__global__ void stats_final_kernel(const int* __restrict__ batch)
{
    int g = threadIdx.x;
    if (g >= NG) return;
    int lo = lb_i(batch, NN, g), hi = lb_i(batch, NN, g + 1);
    int c = hi - lo; if (c < 1) c = 1;
    float denom = (float)c * 110.f;
    float mean = g_sum[g] / denom;
    float var = g_sum2[g] / denom - mean * mean;
    var = fmaxf(var, 0.f);
    g_mean[g] = mean;
    g_rstd[g] = rsqrtf(var + 1e-5f);
}

// -------------------- node stage 1: hid = silu([LN(feats)|m_i] @ W1 + b1) ------------
#define N1_SMEM ((64*144 + 144*128) * 4)
__global__ void node1_kernel(const int* __restrict__ batch,
    const float* __restrict__ nw1, const float* __restrict__ nb1,
    const float* __restrict__ lnw, const float* __restrict__ lnb, int l)
{
    extern __shared__ float sm[];
    float* Xs = sm;             // 64 x 144
    float* Ws = sm + 64 * 144;  // 144 x 128 (rows 142,143 zero)
    int tid = threadIdx.x;
    int m0 = blockIdx.x * 64;

    const float* w1b = nw1 + (size_t)l * NIN * NH;
    for (int i = tid; i < 144 * 32; i += 256) {
        int r = i >> 5, c = (i & 31) * 4;
        float4 w = make_float4(0.f, 0.f, 0.f, 0.f);
        if (r < NIN) w = *(const float4*)&w1b[(size_t)r * NH + c];
        *(float4*)&Ws[r * 128 + c] = w;
    }
    for (int i = tid; i < 64 * 144; i += 256) {
        int n = m0 + i / 144, k = i % 144;
        float v = 0.f;
        if (n < NN) {
            if (k < NF) {
                int g = batch[n];
                float f = g_feats[(size_t)n * FP + k];
                v = lnw[l * NF + k] * ((f - g_mean[g]) * g_rstd[g]) + lnb[l * NF + k];
            } else if (k < NIN) {
                v = g_mi[(size_t)n * MD + (k - NF)];
            }
        }
        Xs[i] = v;
    }
    __syncthreads();

    int tx = tid & 15, ty = tid >> 4;
    float acc[4][8];
    #pragma unroll
    for (int i = 0; i < 4; i++)
        #pragma unroll
        for (int j = 0; j < 8; j++) acc[i][j] = 0.f;

    for (int kt = 0; kt < 36; ++kt) {
        float av[4][4];
        #pragma unroll
        for (int i = 0; i < 4; i++) {
            float4 a = *(const float4*)&Xs[(ty * 4 + i) * 144 + kt * 4];
            av[i][0] = a.x; av[i][1] = a.y; av[i][2] = a.z; av[i][3] = a.w;
        }
        #pragma unroll
        for (int kk = 0; kk < 4; kk++) {
            float4 b0 = *(const float4*)&Ws[(kt * 4 + kk) * 128 + tx * 8];
            float4 b1 = *(const float4*)&Ws[(kt * 4 + kk) * 128 + tx * 8 + 4];
            #pragma unroll
            for (int i = 0; i < 4; i++) {
                float a = av[i][kk];
                acc[i][0] += a * b0.x; acc[i][1] += a * b0.y;
                acc[i][2] += a * b0.z; acc[i][3] += a * b0.w;
                acc[i][4] += a * b1.x; acc[i][5] += a * b1.y;
                acc[i][6] += a * b1.z; acc[i][7] += a * b1.w;
            }
        }
    }
    float bb[8];
    #pragma unroll
    for (int j = 0; j < 8; j++) bb[j] = nb1[l * NH + tx * 8 + j];
    #pragma unroll
    for (int i = 0; i < 4; i++) {
        int n = m0 + ty * 4 + i;
        if (n < NN) {
            float4* p = (float4*)&g_hid[(size_t)n * NH + tx * 8];
            p[0] = make_float4(silu_f(acc[i][0] + bb[0]), silu_f(acc[i][1] + bb[1]),
                               silu_f(acc[i][2] + bb[2]), silu_f(acc[i][3] + bb[3]));
            p[1] = make_float4(silu_f(acc[i][4] + bb[4]), silu_f(acc[i][5] + bb[5]),
                               silu_f(acc[i][6] + bb[6]), silu_f(acc[i][7] + bb[7]));
        }
    }
}

// -------------------- node stage 2: feats += hid @ W2 + b2 ; zero g_mi ------------
#define N2_SMEM ((64*132 + 128*112) * 4)
__global__ void node2_kernel(const float* __restrict__ nw2, const float* __restrict__ nb2, int l)
{
    extern __shared__ float sm[];
    float* Hs = sm;             // 64 x 132
    float* Ws = sm + 64 * 132;  // 128 x 112 (cols 110,111 zero)
    int tid = threadIdx.x;
    int m0 = blockIdx.x * 64;

    const float* w2b = nw2 + (size_t)l * NH * NF;
    for (int i = tid; i < 128 * 112; i += 256) {
        int k = i / 112, c = i % 112;
        Ws[i] = (c < NF) ? w2b[(size_t)k * NF + c] : 0.f;
    }
    for (int i = tid; i < 64 * 32; i += 256) {
        int r = i >> 5, c = (i & 31) * 4;
        int n = m0 + r;
        float4 v = make_float4(0.f, 0.f, 0.f, 0.f);
        if (n < NN) v = *(const float4*)&g_hid[(size_t)n * NH + c];
        *(float4*)&Hs[r * 132 + c] = v;
    }
    __syncthreads();

    int tx = tid & 15, ty = tid >> 4;
    float acc[4][7];
    #pragma unroll
    for (int i = 0; i < 4; i++)
        #pragma unroll
        for (int j = 0; j < 7; j++) acc[i][j] = 0.f;

    for (int kt = 0; kt < 32; ++kt) {
        float av[4][4];
        #pragma unroll
        for (int i = 0; i < 4; i++) {
            float4 a = *(const float4*)&Hs[(ty * 4 + i) * 132 + kt * 4];
            av[i][0] = a.x; av[i][1] = a.y; av[i][2] = a.z; av[i][3] = a.w;
        }
        #pragma unroll
        for (int kk = 0; kk < 4; kk++) {
            #pragma unroll
            for (int j = 0; j < 7; j++) {
                float b = Ws[(kt * 4 + kk) * 112 + tx * 7 + j];
                #pragma unroll
                for (int i = 0; i < 4; i++) acc[i][j] += av[i][kk] * b;
            }
        }
    }
    #pragma unroll
    for (int i = 0; i < 4; i++) {
        int n = m0 + ty * 4 + i;
        if (n < NN) {
            #pragma unroll
            for (int j = 0; j < 7; j++) {
                int c = tx * 7 + j;
                if (c < NF)
                    g_feats[(size_t)n * FP + c] += acc[i][j] + nb2[l * NF + c];
            }
        }
    }
    // re-zero g_mi for the next layer's scatter
    for (int i = tid; i < 64 * MD; i += 256) {
        int n = m0 + i / MD;
        if (n < NN) g_mi[(size_t)n * MD + (i % MD)] = 0.f;
    }
}

// -------------------- global mean pool (coalesced) --------------------
__global__ void pool_kernel(const int* __restrict__ batch, float* __restrict__ out)
{
    __shared__ int s_lo, s_hi;
    __shared__ float red[256];
    int g = blockIdx.x, tid = threadIdx.x;
    if (tid == 0) { s_lo = lb_i(batch, NN, g); s_hi = lb_i(batch, NN, g + 1); }
    __syncthreads();
    float s = 0.f;
    if (tid < 2 * FP) {
        int part = tid / FP;
        int k = tid % FP;
        for (int n = s_lo + part; n < s_hi; n += 2)
            s += g_feats[(size_t)n * FP + k];
    }
    red[tid] = s;
    __syncthreads();
    if (tid < NF) {
        int c = s_hi - s_lo; if (c < 1) c = 1;
        out[g * NF + tid] = (red[tid] + red[tid + FP]) / (float)c;
    }
}

// -------------------- launch --------------------
extern "C" void kernel_launch(void* const* d_in, const int* in_sizes, int n_in,
                              void* d_out, int out_size)
{
    const float* x     = (const float*)d_in[0];
    const int*   ei    = (const int*)  d_in[1];
    const float* eattr = (const float*)d_in[2];
    const float* pos   = (const float*)d_in[3];
    const int*   batch = (const int*)  d_in[4];
    const float* emb[10];
    for (int i = 0; i < 10; i++) emb[i] = (const float*)d_in[5 + i];
    const float* ew1 = (const float*)d_in[15];
    const float* eb1 = (const float*)d_in[16];
    const float* ew2 = (const float*)d_in[17];
    const float* eb2 = (const float*)d_in[18];
    const float* nw1 = (const float*)d_in[19];
    const float* nb1 = (const float*)d_in[20];
    const float* nw2 = (const float*)d_in[21];
    const float* nb2 = (const float*)d_in[22];
    const float* lnw = (const float*)d_in[23];
    const float* lnb = (const float*)d_in[24];
    float* out = (float*)d_out;

    cudaFuncSetAttribute(precompP_kernel, cudaFuncAttributeMaxDynamicSharedMemorySize, PP_SMEM);
    cudaFuncSetAttribute(edge_kernel,     cudaFuncAttributeMaxDynamicSharedMemorySize, EDGE_SMEM);
    cudaFuncSetAttribute(node1_kernel,    cudaFuncAttributeMaxDynamicSharedMemorySize, N1_SMEM);
    cudaFuncSetAttribute(node2_kernel,    cudaFuncAttributeMaxDynamicSharedMemorySize, N2_SMEM);

    embed_kernel<<<(NN * FP + 255) / 256, 256>>>(x, emb[0], emb[1], emb[2], emb[3],
                                                 emb[4], emb[5], emb[6], emb[7], emb[8], emb[9]);
    ea_kernel<<<(NE + 255) / 256, 256>>>(ei, eattr, pos);

    for (int l = 0; l < 2; l++) {
        precompP_kernel<<<dim3((NN + 63) / 64, 2), 256, PP_SMEM>>>(ew1, l);
        stats_partial_kernel<<<dim3(NG, 8), 256>>>(batch);
        stats_final_kernel<<<1, 64>>>(batch);
        edge_kernel<<<(NEL + 127) / 128, 256, EDGE_SMEM>>>(ei, ew1, eb1, ew2, eb2, l);
        node1_kernel<<<(NN + 63) / 64, 256, N1_SMEM>>>(batch, nw1, nb1, lnw, lnb, l);
        node2_kernel<<<(NN + 63) / 64, 256, N2_SMEM>>>(nw2, nb2, l);
    }
    pool_kernel<<<NG, 256>>>(batch, out);
}

// round 3
// speedup vs baseline: 1.5487x; 1.1925x over previous
#include <cuda_runtime.h>
#include <math.h>
#include <stdint.h>

#define NN   50000
#define NE   800000
#define NEL  850000
#define NG   64
#define FP   112      // feats row pitch
#define NF   110
#define MD   32
#define EH   128
#define NH   128
#define NIN  142
#define EFD  222

// -------- device scratch --------
__device__ float g_feats[NN * FP];
__device__ float g_P[(size_t)NN * 256];
__device__ float g_mi[NN * MD];
__device__ float g_ea[NE * 2];
__device__ float g_hid[(size_t)NN * NH];
__device__ float g_sum[NG], g_sum2[NG];
__device__ float g_mean[NG], g_rstd[NG];

__device__ __forceinline__ float silu_f(float x) {
    return x * (1.0f / (1.0f + __expf(-x)));
}
__device__ __forceinline__ uint32_t f2tf(float f) {
    uint32_t u; asm("cvt.rna.tf32.f32 %0, %1;" : "=r"(u) : "f"(f)); return u;
}
__device__ __forceinline__ void mma_tf32(float* d,
    uint32_t a0, uint32_t a1, uint32_t a2, uint32_t a3, uint32_t b0, uint32_t b1)
{
    asm volatile("mma.sync.aligned.m16n8k8.row.col.f32.tf32.tf32.f32 "
        "{%0,%1,%2,%3},{%4,%5,%6,%7},{%8,%9},{%0,%1,%2,%3};"
        : "+f"(d[0]), "+f"(d[1]), "+f"(d[2]), "+f"(d[3])
        : "r"(a0), "r"(a1), "r"(a2), "r"(a3), "r"(b0), "r"(b1));
}
__device__ __forceinline__ int lb_i(const int* __restrict__ a, int n, int v) {
    int lo = 0, hi = n;
    while (lo < hi) { int m = (lo + hi) >> 1; if (a[m] < v) lo = m + 1; else hi = m; }
    return lo;
}

// -------------------- embed (+ zero g_mi) --------------------
__global__ void embed_kernel(const float* __restrict__ x,
    const float* __restrict__ e0, const float* __restrict__ e1,
    const float* __restrict__ e2, const float* __restrict__ e3,
    const float* __restrict__ e4, const float* __restrict__ e5,
    const float* __restrict__ e6, const float* __restrict__ e7,
    const float* __restrict__ e8, const float* __restrict__ e9)
{
    long idx = (long)blockIdx.x * blockDim.x + threadIdx.x;
    if (idx < (long)NN * MD) g_mi[idx] = 0.f;
    if (idx >= (long)NN * FP) return;
    int n = (int)(idx / FP), k = (int)(idx % FP);
    float v = 0.f;
    if (k < 6) {
        int keep = (k == 0) ? 0 : (10 + k);
        v = x[n * 16 + keep];
    } else if (k < 38) {
        int code = (int)x[n * 16 + 1];
        v = e0[code * 32 + (k - 6)];
    } else if (k < 110) {
        int t = (k - 38) >> 3, c = (k - 38) & 7;
        int code = (int)x[n * 16 + 2 + t];
        const float* es[9] = {e1, e2, e3, e4, e5, e6, e7, e8, e9};
        v = es[t][code * 8 + c];
    }
    g_feats[idx] = v;
}

// -------------------- edge attr + rel dist --------------------
__global__ void ea_kernel(const int* __restrict__ ei,
                          const float* __restrict__ eattr,
                          const float* __restrict__ pos)
{
    int e = blockIdx.x * blockDim.x + threadIdx.x;
    if (e >= NE) return;
    int s = ei[e], d = ei[NE + e];
    float dx = pos[s * 3 + 0] - pos[d * 3 + 0];
    float dy = pos[s * 3 + 1] - pos[d * 3 + 1];
    float dz = pos[s * 3 + 2] - pos[d * 3 + 2];
    g_ea[2 * e + 0] = eattr[e];
    g_ea[2 * e + 1] = dx * dx + dy * dy + dz * dz;
}

// ==================== precompP: [64x112] @ [112x128] per half, tf32 MMA ====================
#define PP_LDA 116
#define PP_LDB 136
#define PP_SMEM ((64 * PP_LDA + 112 * PP_LDB) * 4)
__global__ void precompP_kernel(const float* __restrict__ w1, int l)
{
    extern __shared__ float sm[];
    uint32_t* Xs = (uint32_t*)sm;                 // 64 x 116 (tf32 bits)
    uint32_t* Ws = Xs + 64 * PP_LDA;              // 112 x 136
    int tid = threadIdx.x;
    int m0 = blockIdx.x * 64;
    int half = blockIdx.y;

    if (blockIdx.x == 0 && half == 0 && tid < 2 * NG) {
        if (tid < NG) g_sum[tid] = 0.f; else g_sum2[tid - NG] = 0.f;
    }

    const float* wbase = w1 + (size_t)l * EFD * EH + (size_t)half * 110 * EH;
    for (int i = tid; i < 112 * PP_LDB; i += 256) {
        int k = i / PP_LDB, c = i % PP_LDB;
        Ws[i] = (k < 110 && c < 128) ? f2tf(wbase[(size_t)k * EH + c]) : 0u;
    }
    for (int i = tid; i < 64 * PP_LDA; i += 256) {
        int r = i / PP_LDA, c = i % PP_LDA;
        int n = m0 + r;
        Xs[i] = (n < NN && c < FP) ? f2tf(g_feats[(size_t)n * FP + c]) : 0u;
    }
    __syncthreads();

    int w = tid >> 5, lane = tid & 31;
    int g = lane >> 2, tig = lane & 3;
    int mp = w & 1;          // m rows mp*32 .. +31
    int ng = w >> 1;         // n cols ng*32 .. +31
    float acc[2][4][4];
    #pragma unroll
    for (int mi = 0; mi < 2; mi++)
        #pragma unroll
        for (int j = 0; j < 4; j++)
            #pragma unroll
            for (int q = 0; q < 4; q++) acc[mi][j][q] = 0.f;

    #pragma unroll 2
    for (int k0 = 0; k0 < 112; k0 += 8) {
        uint32_t a[2][4];
        #pragma unroll
        for (int mi = 0; mi < 2; mi++) {
            int r0 = mp * 32 + mi * 16;
            a[mi][0] = Xs[(r0 + g) * PP_LDA + k0 + tig];
            a[mi][1] = Xs[(r0 + g + 8) * PP_LDA + k0 + tig];
            a[mi][2] = Xs[(r0 + g) * PP_LDA + k0 + tig + 4];
            a[mi][3] = Xs[(r0 + g + 8) * PP_LDA + k0 + tig + 4];
        }
        uint32_t b[4][2];
        #pragma unroll
        for (int j = 0; j < 4; j++) {
            int c0 = ng * 32 + j * 8 + g;
            b[j][0] = Ws[(k0 + tig) * PP_LDB + c0];
            b[j][1] = Ws[(k0 + tig + 4) * PP_LDB + c0];
        }
        #pragma unroll
        for (int mi = 0; mi < 2; mi++)
            #pragma unroll
            for (int j = 0; j < 4; j++)
                mma_tf32(acc[mi][j], a[mi][0], a[mi][1], a[mi][2], a[mi][3], b[j][0], b[j][1]);
    }

    #pragma unroll
    for (int mi = 0; mi < 2; mi++) {
        int r = m0 + mp * 32 + mi * 16 + g;
        #pragma unroll
        for (int j = 0; j < 4; j++) {
            int col = half * 128 + ng * 32 + j * 8 + 2 * tig;
            if (r < NN)
                *(float2*)&g_P[(size_t)r * 256 + col] = make_float2(acc[mi][j][0], acc[mi][j][1]);
            if (r + 8 < NN)
                *(float2*)&g_P[(size_t)(r + 8) * 256 + col] = make_float2(acc[mi][j][2], acc[mi][j][3]);
        }
    }
}

// ==================== edge: gather + silu (fp32) -> tf32 MMA -> scatter ====================
#define E_LDA 132
#define E_LDB 40
#define E_LDM 36
// floats: Hs 128*132 | W2s 128*40 | w220 128 | w221 128 | b1s 128 | b2s 32 | ea0s 128 | dds 128 | ints 256
#define EDGE_SMEM ((128 * E_LDA + 128 * E_LDB + 128 * 3 + 32 + 128 + 128 + 256) * 4)
__global__ void edge_kernel(const int* __restrict__ ei,
    const float* __restrict__ w1, const float* __restrict__ b1,
    const float* __restrict__ w2, const float* __restrict__ b2, int l)
{
    extern __shared__ float sm[];
    float* Hs   = sm;                       // 128 x 132 (tf32 bits); later reused as Ms 128 x 36
    float* W2s  = Hs + 128 * E_LDA;         // 128 x 40 (tf32 bits)
    float* w220 = W2s + 128 * E_LDB;
    float* w221 = w220 + 128;
    float* b1s  = w221 + 128;
    float* b2s  = b1s + 128;
    float* ea0s = b2s + 32;
    float* dds  = ea0s + 128;
    int*   srcs = (int*)(dds + 128);
    int*   dsts = srcs + 128;
    uint32_t* HsU = (uint32_t*)Hs;
    uint32_t* WU  = (uint32_t*)W2s;
    float* Ms = Hs;                         // reuse after phase 2

    int tid = threadIdx.x;
    int e0 = blockIdx.x * 128;
    const float* w1b = w1 + (size_t)l * EFD * EH;

    if (tid < 128) {
        w220[tid] = w1b[220 * EH + tid];
        w221[tid] = w1b[221 * EH + tid];
        b1s[tid]  = b1[l * EH + tid];
        int e = e0 + tid;
        int s = -1, d = -1; float a = 0.f, dd = 0.f;
        if (e < NEL) {
            if (e < NE) { s = ei[e]; d = ei[NE + e]; a = g_ea[2 * e]; dd = g_ea[2 * e + 1]; }
            else        { s = d = e - NE; }
        }
        srcs[tid] = s; dsts[tid] = d; ea0s[tid] = a; dds[tid] = dd;
    } else if (tid < 160) {
        b2s[tid - 128] = b2[l * MD + (tid - 128)];
    }
    for (int i = tid; i < 128 * 32; i += 256) {
        int k = i >> 5, c = i & 31;
        WU[k * E_LDB + c] = f2tf(w2[(size_t)l * EH * MD + i]);
    }
    __syncthreads();

    // phase 1: H = silu(Pd[dst] + Ps[src] + ea*w220 + dist*w221 + b1), tf32-rounded into smem
    #pragma unroll
    for (int it = 0; it < 16; ++it) {
        int idx = it * 256 + tid;
        int e = idx >> 5;
        int k0 = (idx & 31) * 4;
        int d = dsts[e];
        uint4 u = make_uint4(0u, 0u, 0u, 0u);
        if (d >= 0) {
            int s = srcs[e];
            float4 pd = *(const float4*)&g_P[(size_t)d * 256 + k0];
            float4 ps = *(const float4*)&g_P[(size_t)s * 256 + 128 + k0];
            float a = ea0s[e], dd = dds[e];
            u.x = f2tf(silu_f(pd.x + ps.x + a * w220[k0 + 0] + dd * w221[k0 + 0] + b1s[k0 + 0]));
            u.y = f2tf(silu_f(pd.y + ps.y + a * w220[k0 + 1] + dd * w221[k0 + 1] + b1s[k0 + 1]));
            u.z = f2tf(silu_f(pd.z + ps.z + a * w220[k0 + 2] + dd * w221[k0 + 2] + b1s[k0 + 2]));
            u.w = f2tf(silu_f(pd.w + ps.w + a * w220[k0 + 3] + dd * w221[k0 + 3] + b1s[k0 + 3]));
        }
        *(uint4*)&HsU[e * E_LDA + k0] = u;
    }
    __syncthreads();

    // phase 2: tf32 MMA, [128 x 128] @ [128 x 32]
    int w = tid >> 5, lane = tid & 31;
    int g = lane >> 2, tig = lane & 3;
    int mp = w & 3;          // rows mp*32 .. +31
    int np = w >> 2;         // cols np*16 .. +15
    float acc[2][2][4];
    #pragma unroll
    for (int mi = 0; mi < 2; mi++)
        #pragma unroll
        for (int ni = 0; ni < 2; ni++)
            #pragma unroll
            for (int q = 0; q < 4; q++) acc[mi][ni][q] = 0.f;

    #pragma unroll 2
    for (int k0 = 0; k0 < 128; k0 += 8) {
        uint32_t a[2][4];
        #pragma unroll
        for (int mi = 0; mi < 2; mi++) {
            int r0 = mp * 32 + mi * 16;
            a[mi][0] = HsU[(r0 + g) * E_LDA + k0 + tig];
            a[mi][1] = HsU[(r0 + g + 8) * E_LDA + k0 + tig];
            a[mi][2] = HsU[(r0 + g) * E_LDA + k0 + tig + 4];
            a[mi][3] = HsU[(r0 + g + 8) * E_LDA + k0 + tig + 4];
        }
        uint32_t b[2][2];
        #pragma unroll
        for (int ni = 0; ni < 2; ni++) {
            int c0 = np * 16 + ni * 8 + g;
            b[ni][0] = WU[(k0 + tig) * E_LDB + c0];
            b[ni][1] = WU[(k0 + tig + 4) * E_LDB + c0];
        }
        #pragma unroll
        for (int mi = 0; mi < 2; mi++)
            #pragma unroll
            for (int ni = 0; ni < 2; ni++)
                mma_tf32(acc[mi][ni], a[mi][0], a[mi][1], a[mi][2], a[mi][3], b[ni][0], b[ni][1]);
    }
    __syncthreads();   // done reading Hs; reuse as Ms

    #pragma unroll
    for (int mi = 0; mi < 2; mi++) {
        int r = mp * 32 + mi * 16 + g;
        #pragma unroll
        for (int ni = 0; ni < 2; ni++) {
            int c = np * 16 + ni * 8 + 2 * tig;
            Ms[r * E_LDM + c]           = silu_f(acc[mi][ni][0] + b2s[c]);
            Ms[r * E_LDM + c + 1]       = silu_f(acc[mi][ni][1] + b2s[c + 1]);
            Ms[(r + 8) * E_LDM + c]     = silu_f(acc[mi][ni][2] + b2s[c]);
            Ms[(r + 8) * E_LDM + c + 1] = silu_f(acc[mi][ni][3] + b2s[c + 1]);
        }
    }
    __syncthreads();

    // scatter: 2 threads per edge, 4 float4 RED each
    int e = tid >> 1;
    int cb = (tid & 1) * 16;
    int d = dsts[e];
    if (d >= 0) {
        #pragma unroll
        for (int q = 0; q < 4; q++) {
            float4 v = *(const float4*)&Ms[e * E_LDM + cb + q * 4];
            atomicAdd((float4*)&g_mi[(size_t)d * MD + cb + q * 4], v);
        }
    }
}

// -------------------- LN stats --------------------
__global__ void stats_partial_kernel(const int* __restrict__ batch)
{
    __shared__ int s_lo, s_hi;
    __shared__ float rs[8], rs2[8];
    int g = blockIdx.x, part = blockIdx.y;
    int tid = threadIdx.x;
    if (tid == 0) { s_lo = lb_i(batch, NN, g); s_hi = lb_i(batch, NN, g + 1); }
    __syncthreads();
    int total = (s_hi - s_lo) * FP;
    int chunk = (total + 7) >> 3;
    int st = part * chunk;
    int en = st + chunk; if (en > total) en = total;
    const float* base = g_feats + (size_t)s_lo * FP;
    float s = 0.f, s2 = 0.f;
    for (int i = st + tid; i < en; i += 256) { float v = base[i]; s += v; s2 += v * v; }
    #pragma unroll
    for (int o = 16; o; o >>= 1) {
        s  += __shfl_down_sync(0xffffffffu, s, o);
        s2 += __shfl_down_sync(0xffffffffu, s2, o);
    }
    if ((tid & 31) == 0) { rs[tid >> 5] = s; rs2[tid >> 5] = s2; }
    __syncthreads();
    if (tid == 0) {
        float a = 0.f, b = 0.f;
        for (int i = 0; i < 8; i++) { a += rs[i]; b += rs2[i]; }
        atomicAdd(&g_sum[g], a); atomicAdd(&g_sum2[g], b);
    }
}

__global__ void stats_final_kernel(const int* __restrict__ batch)
{
    int g = threadIdx.x;
    if (g >= NG) return;
    int lo = lb_i(batch, NN, g), hi = lb_i(batch, NN, g + 1);
    int c = hi - lo; if (c < 1) c = 1;
    float denom = (float)c * 110.f;
    float mean = g_sum[g] / denom;
    float var = g_sum2[g] / denom - mean * mean;
    var = fmaxf(var, 0.f);
    g_mean[g] = mean;
    g_rstd[g] = rsqrtf(var + 1e-5f);
}

// ==================== node1: [64x144] @ [144x64] per half, tf32 MMA ====================
#define N1_LDA 148
#define N1_LDB 72
#define N1_SMEM ((64 * N1_LDA + 144 * N1_LDB) * 4)
__global__ void node1_kernel(const int* __restrict__ batch,
    const float* __restrict__ nw1, const float* __restrict__ nb1,
    const float* __restrict__ lnw, const float* __restrict__ lnb, int l)
{
    extern __shared__ float sm[];
    uint32_t* Xs = (uint32_t*)sm;                 // 64 x 148
    uint32_t* Ws = Xs + 64 * N1_LDA;              // 144 x 72
    int tid = threadIdx.x;
    int m0 = blockIdx.x * 64;
    int half = blockIdx.y;                        // output cols half*64 .. +63

    const float* w1b = nw1 + (size_t)l * NIN * NH;
    for (int i = tid; i < 144 * N1_LDB; i += 256) {
        int k = i / N1_LDB, c = i % N1_LDB;
        Ws[i] = (k < NIN && c < 64) ? f2tf(w1b[(size_t)k * NH + half * 64 + c]) : 0u;
    }
    for (int i = tid; i < 64 * N1_LDA; i += 256) {
        int n = m0 + i / N1_LDA, k = i % N1_LDA;
        float v = 0.f;
        if (n < NN) {
            if (k < NF) {
                int gg = batch[n];
                float f = g_feats[(size_t)n * FP + k];
                v = lnw[l * NF + k] * ((f - g_mean[gg]) * g_rstd[gg]) + lnb[l * NF + k];
            } else if (k < NIN) {
                v = g_mi[(size_t)n * MD + (k - NF)];
            }
        }
        Xs[i] = f2tf(v);
    }
    __syncthreads();

    int w = tid >> 5, lane = tid & 31;
    int g = lane >> 2, tig = lane & 3;
    int mp = w & 1;          // rows mp*32 .. +31
    int np = w >> 1;         // cols np*16 .. +15
    float acc[2][2][4];
    #pragma unroll
    for (int mi = 0; mi < 2; mi++)
        #pragma unroll
        for (int ni = 0; ni < 2; ni++)
            #pragma unroll
            for (int q = 0; q < 4; q++) acc[mi][ni][q] = 0.f;

    #pragma unroll 2
    for (int k0 = 0; k0 < 144; k0 += 8) {
        uint32_t a[2][4];
        #pragma unroll
        for (int mi = 0; mi < 2; mi++) {
            int r0 = mp * 32 + mi * 16;
            a[mi][0] = Xs[(r0 + g) * N1_LDA + k0 + tig];
            a[mi][1] = Xs[(r0 + g + 8) * N1_LDA + k0 + tig];
            a[mi][2] = Xs[(r0 + g) * N1_LDA + k0 + tig + 4];
            a[mi][3] = Xs[(r0 + g + 8) * N1_LDA + k0 + tig + 4];
        }
        uint32_t b[2][2];
        #pragma unroll
        for (int ni = 0; ni < 2; ni++) {
            int c0 = np * 16 + ni * 8 + g;
            b[ni][0] = Ws[(k0 + tig) * N1_LDB + c0];
            b[ni][1] = Ws[(k0 + tig + 4) * N1_LDB + c0];
        }
        #pragma unroll
        for (int mi = 0; mi < 2; mi++)
            #pragma unroll
            for (int ni = 0; ni < 2; ni++)
                mma_tf32(acc[mi][ni], a[mi][0], a[mi][1], a[mi][2], a[mi][3], b[ni][0], b[ni][1]);
    }

    #pragma unroll
    for (int mi = 0; mi < 2; mi++) {
        int r = m0 + mp * 32 + mi * 16 + g;
        #pragma unroll
        for (int ni = 0; ni < 2; ni++) {
            int cg = half * 64 + np * 16 + ni * 8 + 2 * tig;
            float bb0 = nb1[l * NH + cg], bb1 = nb1[l * NH + cg + 1];
            if (r < NN)
                *(float2*)&g_hid[(size_t)r * NH + cg] =
                    make_float2(silu_f(acc[mi][ni][0] + bb0), silu_f(acc[mi][ni][1] + bb1));
            if (r + 8 < NN)
                *(float2*)&g_hid[(size_t)(r + 8) * NH + cg] =
                    make_float2(silu_f(acc[mi][ni][2] + bb0), silu_f(acc[mi][ni][3] + bb1));
        }
    }
}

// -------------------- node2: feats += hid @ W2 + b2 (fp32) ; zero g_mi ------------
#define N2_SMEM ((64 * 132 + 128 * 112) * 4)
__global__ void node2_kernel(const float* __restrict__ nw2, const float* __restrict__ nb2, int l)
{
    extern __shared__ float sm[];
    float* Hs = sm;             // 64 x 132
    float* Ws = sm + 64 * 132;  // 128 x 112
    int tid = threadIdx.x;
    int m0 = blockIdx.x * 64;

    const float* w2b = nw2 + (size_t)l * NH * NF;
    for (int i = tid; i < 128 * 112; i += 256) {
        int k = i / 112, c = i % 112;
        Ws[i] = (c < NF) ? w2b[(size_t)k * NF + c] : 0.f;
    }
    for (int i = tid; i < 64 * 32; i += 256) {
        int r = i >> 5, c = (i & 31) * 4;
        int n = m0 + r;
        float4 v = make_float4(0.f, 0.f, 0.f, 0.f);
        if (n < NN) v = *(const float4*)&g_hid[(size_t)n * NH + c];
        *(float4*)&Hs[r * 132 + c] = v;
    }
    __syncthreads();

    int tx = tid & 15, ty = tid >> 4;
    float acc[4][7];
    #pragma unroll
    for (int i = 0; i < 4; i++)
        #pragma unroll
        for (int j = 0; j < 7; j++) acc[i][j] = 0.f;

    for (int kt = 0; kt < 32; ++kt) {
        float av[4][4];
        #pragma unroll
        for (int i = 0; i < 4; i++) {
            float4 a = *(const float4*)&Hs[(ty * 4 + i) * 132 + kt * 4];
            av[i][0] = a.x; av[i][1] = a.y; av[i][2] = a.z; av[i][3] = a.w;
        }
        #pragma unroll
        for (int kk = 0; kk < 4; kk++) {
            #pragma unroll
            for (int j = 0; j < 7; j++) {
                float b = Ws[(kt * 4 + kk) * 112 + tx * 7 + j];
                #pragma unroll
                for (int i = 0; i < 4; i++) acc[i][j] += av[i][kk] * b;
            }
        }
    }
    #pragma unroll
    for (int i = 0; i < 4; i++) {
        int n = m0 + ty * 4 + i;
        if (n < NN) {
            #pragma unroll
            for (int j = 0; j < 7; j++) {
                int c = tx * 7 + j;
                if (c < NF)
                    g_feats[(size_t)n * FP + c] += acc[i][j] + nb2[l * NF + c];
            }
        }
    }
    for (int i = tid; i < 64 * MD; i += 256) {
        int n = m0 + i / MD;
        if (n < NN) g_mi[(size_t)n * MD + (i % MD)] = 0.f;
    }
}

// -------------------- global mean pool --------------------
__global__ void pool_kernel(const int* __restrict__ batch, float* __restrict__ out)
{
    __shared__ int s_lo, s_hi;
    __shared__ float red[256];
    int g = blockIdx.x, tid = threadIdx.x;
    if (tid == 0) { s_lo = lb_i(batch, NN, g); s_hi = lb_i(batch, NN, g + 1); }
    __syncthreads();
    float s = 0.f;
    if (tid < 2 * FP) {
        int part = tid / FP;
        int k = tid % FP;
        for (int n = s_lo + part; n < s_hi; n += 2)
            s += g_feats[(size_t)n * FP + k];
    }
    red[tid] = s;
    __syncthreads();
    if (tid < NF) {
        int c = s_hi - s_lo; if (c < 1) c = 1;
        out[g * NF + tid] = (red[tid] + red[tid + FP]) / (float)c;
    }
}

// -------------------- launch --------------------
extern "C" void kernel_launch(void* const* d_in, const int* in_sizes, int n_in,
                              void* d_out, int out_size)
{
    const float* x     = (const float*)d_in[0];
    const int*   ei    = (const int*)  d_in[1];
    const float* eattr = (const float*)d_in[2];
    const float* pos   = (const float*)d_in[3];
    const int*   batch = (const int*)  d_in[4];
    const float* emb[10];
    for (int i = 0; i < 10; i++) emb[i] = (const float*)d_in[5 + i];
    const float* ew1 = (const float*)d_in[15];
    const float* eb1 = (const float*)d_in[16];
    const float* ew2 = (const float*)d_in[17];
    const float* eb2 = (const float*)d_in[18];
    const float* nw1 = (const float*)d_in[19];
    const float* nb1 = (const float*)d_in[20];
    const float* nw2 = (const float*)d_in[21];
    const float* nb2 = (const float*)d_in[22];
    const float* lnw = (const float*)d_in[23];
    const float* lnb = (const float*)d_in[24];
    float* out = (float*)d_out;

    cudaFuncSetAttribute(precompP_kernel, cudaFuncAttributeMaxDynamicSharedMemorySize, PP_SMEM);
    cudaFuncSetAttribute(edge_kernel,     cudaFuncAttributeMaxDynamicSharedMemorySize, EDGE_SMEM);
    cudaFuncSetAttribute(node1_kernel,    cudaFuncAttributeMaxDynamicSharedMemorySize, N1_SMEM);
    cudaFuncSetAttribute(node2_kernel,    cudaFuncAttributeMaxDynamicSharedMemorySize, N2_SMEM);

    embed_kernel<<<(NN * FP + 255) / 256, 256>>>(x, emb[0], emb[1], emb[2], emb[3],
                                                 emb[4], emb[5], emb[6], emb[7], emb[8], emb[9]);
    ea_kernel<<<(NE + 255) / 256, 256>>>(ei, eattr, pos);

    for (int l = 0; l < 2; l++) {
        precompP_kernel<<<dim3((NN + 63) / 64, 2), 256, PP_SMEM>>>(ew1, l);
        stats_partial_kernel<<<dim3(NG, 8), 256>>>(batch);
        stats_final_kernel<<<1, 64>>>(batch);
        edge_kernel<<<(NEL + 127) / 128, 256, EDGE_SMEM>>>(ei, ew1, eb1, ew2, eb2, l);
        node1_kernel<<<dim3((NN + 63) / 64, 2), 256, N1_SMEM>>>(batch, nw1, nb1, lnw, lnb, l);
        node2_kernel<<<(NN + 63) / 64, 256, N2_SMEM>>>(nw2, nb2, l);
    }
    pool_kernel<<<NG, 256>>>(batch, out);
}